// round 5
// baseline (speedup 1.0000x reference)
#include <cuda_runtime.h>
#include <math.h>

#define BATCH 16
#define DIM   48
#define HID   16
#define CH    8
#define IMG   256
#define HW    (IMG*IMG)
#define ROWS  (BATCH*HW)

typedef unsigned long long u64;

__device__ float g_x1[(size_t)ROWS * CH];   // 33.5 MB
__device__ float g_n [(size_t)ROWS * CH];   // 33.5 MB

__device__ __forceinline__ u64 pk2(float a, float b) {
    u64 r;
    asm("mov.b64 %0,{%1,%2};" : "=l"(r) : "r"(__float_as_uint(a)), "r"(__float_as_uint(b)));
    return r;
}
__device__ __forceinline__ void upk2(u64 v, float& a, float& b) {
    unsigned lo, hi;
    asm("mov.b64 {%0,%1},%2;" : "=r"(lo), "=r"(hi) : "l"(v));
    a = __uint_as_float(lo); b = __uint_as_float(hi);
}
__device__ __forceinline__ void fma2(u64& d, u64 a, u64 b) {
    asm("fma.rn.f32x2 %0,%1,%2,%0;" : "+l"(d) : "l"(a), "l"(b));
}

// Exact-formula GELU via A&S 7.1.26 erf (|abs err| ~1.5e-7, validated R3/R4)
__device__ __forceinline__ float gelu_f(float v) {
    float s = fabsf(v) * 0.7071067811865476f;
    float t = __fdividef(1.0f, fmaf(0.3275911f, s, 1.0f));
    float p = fmaf(1.061405429f, t, -1.453152027f);
    p = fmaf(p, t, 1.421413741f);
    p = fmaf(p, t, -0.284496736f);
    p = fmaf(p, t, 0.254829592f);
    p *= t;
    float e = fmaf(-p, __expf(-s * s), 1.0f);
    e = copysignf(e, v);
    return 0.5f * v * (1.0f + e);
}

// ---------------------------------------------------------------------------
// K1: t = gelu(gelu(x @ W1 + b1)); x1 = t[:,:8]; n = LN(t[:,8:])
// Packed f32x2 accumulators (16 regs), scalar GELU, 64-reg cap.
// ---------------------------------------------------------------------------
__global__ __launch_bounds__(256, 4) void k1_gemm_gelu_ln(
    const float* __restrict__ x, const float* __restrict__ W1,
    const float* __restrict__ b1, const float* __restrict__ gamma,
    const float* __restrict__ beta)
{
    __shared__ __align__(16) float sW1[DIM * HID];
    __shared__ u64  sb1_2[HID / 2];
    __shared__ float sg[CH], sb[CH];

    int tid = threadIdx.x;
    for (int i = tid; i < DIM * HID; i += 256) sW1[i] = W1[i];
    if (tid < HID / 2) sb1_2[tid] = pk2(b1[2 * tid], b1[2 * tid + 1]);
    if (tid < CH) { sg[tid] = gamma[tid]; sb[tid] = beta[tid]; }
    __syncthreads();

    int r = blockIdx.x * 256 + tid;
    const float4* xr = (const float4*)(x + (size_t)r * DIM);

    u64 z2[8];
    #pragma unroll
    for (int q = 0; q < 8; q++) z2[q] = sb1_2[q];

    #pragma unroll
    for (int k4 = 0; k4 < DIM / 4; k4++) {
        float4 v = xr[k4];
        float xs[4] = {v.x, v.y, v.z, v.w};
        #pragma unroll
        for (int kk = 0; kk < 4; kk++) {
            u64 xx = pk2(xs[kk], xs[kk]);
            const ulonglong2* wr = (const ulonglong2*)&sW1[(k4 * 4 + kk) * HID];
            #pragma unroll
            for (int q2 = 0; q2 < 4; q2++) {
                ulonglong2 w = wr[q2];
                fma2(z2[2 * q2],     xx, w.x);
                fma2(z2[2 * q2 + 1], xx, w.y);
            }
        }
    }

    float z[HID];
    #pragma unroll
    for (int q = 0; q < 8; q++) upk2(z2[q], z[2 * q], z[2 * q + 1]);

    #pragma unroll
    for (int j = 0; j < HID; j++) z[j] = gelu_f(gelu_f(z[j]));

    float4* o1 = (float4*)(g_x1 + (size_t)r * CH);
    o1[0] = make_float4(z[0], z[1], z[2], z[3]);
    o1[1] = make_float4(z[4], z[5], z[6], z[7]);

    float m = 0.f;
    #pragma unroll
    for (int j = 8; j < 16; j++) m += z[j];
    m *= 0.125f;
    float var = 0.f;
    #pragma unroll
    for (int j = 8; j < 16; j++) { float d = z[j] - m; var += d * d; }
    var *= 0.125f;
    float inv = rsqrtf(var + 1e-5f);

    float nn[CH];
    #pragma unroll
    for (int j = 0; j < CH; j++) nn[j] = (z[8 + j] - m) * inv * sg[j] + sb[j];

    float4* o2 = (float4*)(g_n + (size_t)r * CH);
    o2[0] = make_float4(nn[0], nn[1], nn[2], nn[3]);
    o2[1] = make_float4(nn[4], nn[5], nn[6], nn[7]);
}

// ---------------------------------------------------------------------------
// K2: all-scalar FMA, all LDS.128 via transposed weights.
// Phase 2a: dw3x3 + pw1x1 + gate -> g parked in smem.
// Phase 2b: GEMM 8->48, 4 px/thread, STG.128 transposed stores.
// ---------------------------------------------------------------------------
#define TX 32
#define TY 16
#define HAW (TX+2)
#define HAH (TY+2)
#define NH  (HAW*HAH)     // 612
#define NT  256
#define NPIX (TX*TY)      // 512

__global__ __launch_bounds__(NT, 4) void k2_conv_gate_gemm(
    const float* __restrict__ dw_w, const float* __restrict__ dw_b,
    const float* __restrict__ pw_w, const float* __restrict__ pw_b,
    const float* __restrict__ W2,   const float* __restrict__ b2,
    float* __restrict__ out)
{
    __shared__ float4 snA[NH], snB[NH];                 // 19.6 KB
    __shared__ float4 sgA[NPIX], sgB[NPIX];             // 16 KB
    __shared__ __align__(16) float sdwT[9 * CH];        // [tap][c]
    __shared__ __align__(16) float spwT[CH * CH];       // [cin][cout]
    __shared__ __align__(16) float sW2T[DIM * CH];      // [d][c]
    __shared__ float sdwb[CH], spwb[CH], sb2[DIM];

    const int tid = threadIdx.x;

    for (int i = tid; i < 9 * CH; i += NT) {            // dwT[tap][c]
        int tap = i / CH, c = i % CH;
        sdwT[i] = dw_w[c * 9 + tap];
    }
    for (int i = tid; i < CH * CH; i += NT) {           // pwT[cin][cout]
        int ci = i / CH, co = i % CH;
        spwT[i] = pw_w[co * CH + ci];
    }
    for (int i = tid; i < DIM * CH; i += NT) {          // W2T[d][c]
        int d = i / CH, c = i % CH;
        sW2T[i] = W2[c * DIM + d];
    }
    if (tid < CH)                 sdwb[tid] = dw_b[tid];
    else if (tid >= 32 && tid < 40) spwb[tid - 32] = pw_b[tid - 32];
    if (tid >= 64 && tid < 112)   sb2[tid - 64] = b2[tid - 64];

    const int b   = blockIdx.z;
    const int tx0 = blockIdx.x * TX;
    const int ty0 = blockIdx.y * TY;
    const float* nb = g_n + (size_t)b * HW * CH;

    // halo load of n
    for (int i = tid; i < NH; i += NT) {
        int hy = i / HAW, hx = i % HAW;
        int gy = ty0 + hy - 1, gx = tx0 + hx - 1;
        float4 a = make_float4(0.f, 0.f, 0.f, 0.f);
        float4 c = make_float4(0.f, 0.f, 0.f, 0.f);
        if (((unsigned)gy < IMG) & ((unsigned)gx < IMG)) {
            const float4* src = (const float4*)(nb + ((size_t)gy * IMG + gx) * CH);
            a = src[0]; c = src[1];
        }
        snA[i] = a; snB[i] = c;
    }
    __syncthreads();

    const float4* sdwT4 = (const float4*)sdwT;
    const float4* spwT4 = (const float4*)spwT;
    const float4* sW2T4 = (const float4*)sW2T;

    // ---- phase 2a: conv + pw + gate -> g in smem (2 px/thread) ----
    #pragma unroll
    for (int rep = 0; rep < NPIX / NT; rep++) {
        int o  = tid + rep * NT;
        int oy = o / TX, ox = o % TX;
        int ci = (oy + 1) * HAW + (ox + 1);

        float sp[CH];
        #pragma unroll
        for (int c = 0; c < CH; c++) sp[c] = sdwb[c];
        float nc[CH];

        #pragma unroll
        for (int dy = 0; dy < 3; dy++) {
            #pragma unroll
            for (int dx = 0; dx < 3; dx++) {
                int tap = dy * 3 + dx;
                int idx = ci + (dy - 1) * HAW + (dx - 1);
                float4 a  = snA[idx];
                float4 bv = snB[idx];
                float4 wA = sdwT4[tap * 2];
                float4 wB = sdwT4[tap * 2 + 1];
                sp[0] += a.x  * wA.x; sp[1] += a.y  * wA.y;
                sp[2] += a.z  * wA.z; sp[3] += a.w  * wA.w;
                sp[4] += bv.x * wB.x; sp[5] += bv.y * wB.y;
                sp[6] += bv.z * wB.z; sp[7] += bv.w * wB.w;
                if (tap == 4) {
                    nc[0] = a.x;  nc[1] = a.y;  nc[2] = a.z;  nc[3] = a.w;
                    nc[4] = bv.x; nc[5] = bv.y; nc[6] = bv.z; nc[7] = bv.w;
                }
            }
        }

        float chv[CH];
        #pragma unroll
        for (int c = 0; c < CH; c++) chv[c] = spwb[c];
        #pragma unroll
        for (int i = 0; i < CH; i++) {
            float v = nc[i];
            float4 wA = spwT4[i * 2];
            float4 wB = spwT4[i * 2 + 1];
            chv[0] += v * wA.x; chv[1] += v * wA.y;
            chv[2] += v * wA.z; chv[3] += v * wA.w;
            chv[4] += v * wB.x; chv[5] += v * wB.y;
            chv[6] += v * wB.z; chv[7] += v * wB.w;
        }

        int p = (ty0 + oy) * IMG + (tx0 + ox);
        const float4* x1p = (const float4*)(g_x1 + ((size_t)b * HW + p) * CH);
        float4 xa = x1p[0], xv = x1p[1];
        sgA[o] = make_float4(xa.x * sp[0] * chv[0], xa.y * sp[1] * chv[1],
                             xa.z * sp[2] * chv[2], xa.w * sp[3] * chv[3]);
        sgB[o] = make_float4(xv.x * sp[4] * chv[4], xv.y * sp[5] * chv[5],
                             xv.z * sp[6] * chv[6], xv.w * sp[7] * chv[7]);
    }
    __syncthreads();

    // ---- phase 2b: GEMM 8->48, 4 consecutive px/thread, 24 d's each ----
    {
        int half = tid >> 7;            // 0/1 -> d in [0,24) / [24,48)
        int pg   = tid & 127;           // 128 pixel-groups of 4
        int oy   = pg >> 3, ox4 = (pg & 7) * 4;
        int o0   = oy * TX + ox4;

        float g0[CH], g1[CH], g2[CH], g3[CH];
        {
            float4 a, v;
            a = sgA[o0 + 0]; v = sgB[o0 + 0];
            g0[0]=a.x; g0[1]=a.y; g0[2]=a.z; g0[3]=a.w; g0[4]=v.x; g0[5]=v.y; g0[6]=v.z; g0[7]=v.w;
            a = sgA[o0 + 1]; v = sgB[o0 + 1];
            g1[0]=a.x; g1[1]=a.y; g1[2]=a.z; g1[3]=a.w; g1[4]=v.x; g1[5]=v.y; g1[6]=v.z; g1[7]=v.w;
            a = sgA[o0 + 2]; v = sgB[o0 + 2];
            g2[0]=a.x; g2[1]=a.y; g2[2]=a.z; g2[3]=a.w; g2[4]=v.x; g2[5]=v.y; g2[6]=v.z; g2[7]=v.w;
            a = sgA[o0 + 3]; v = sgB[o0 + 3];
            g3[0]=a.x; g3[1]=a.y; g3[2]=a.z; g3[3]=a.w; g3[4]=v.x; g3[5]=v.y; g3[6]=v.z; g3[7]=v.w;
        }

        int prow = (ty0 + oy) * IMG + tx0 + ox4;
        float* ob = out + (size_t)b * DIM * HW + prow;

        #pragma unroll
        for (int dd = 0; dd < DIM / 2; dd++) {
            int d = half * (DIM / 2) + dd;
            float4 wA = sW2T4[d * 2], wB = sW2T4[d * 2 + 1];
            float w[CH] = {wA.x, wA.y, wA.z, wA.w, wB.x, wB.y, wB.z, wB.w};
            float bb = sb2[d];
            float a0 = bb, a1 = bb, a2 = bb, a3 = bb;
            #pragma unroll
            for (int c = 0; c < CH; c++) {
                a0 = fmaf(g0[c], w[c], a0);
                a1 = fmaf(g1[c], w[c], a1);
                a2 = fmaf(g2[c], w[c], a2);
                a3 = fmaf(g3[c], w[c], a3);
            }
            *(float4*)(ob + (size_t)d * HW) = make_float4(a0, a1, a2, a3);
        }
    }
}

extern "C" void kernel_launch(void* const* d_in, const int* in_sizes, int n_in,
                              void* d_out, int out_size)
{
    const float* x     = (const float*)d_in[0];
    const float* W1    = (const float*)d_in[1];
    const float* b1    = (const float*)d_in[2];
    const float* gamma = (const float*)d_in[3];
    const float* beta  = (const float*)d_in[4];
    const float* dw_w  = (const float*)d_in[5];
    const float* dw_b  = (const float*)d_in[6];
    const float* pw_w  = (const float*)d_in[7];
    const float* pw_b  = (const float*)d_in[8];
    const float* W2    = (const float*)d_in[9];
    const float* b2    = (const float*)d_in[10];
    float* out = (float*)d_out;

    k1_gemm_gelu_ln<<<ROWS / 256, 256>>>(x, W1, b1, gamma, beta);

    dim3 g2(IMG / TX, IMG / TY, BATCH);
    k2_conv_gate_gemm<<<g2, NT>>>(dw_w, dw_b, pw_w, pw_b, W2, b2, out);
}

// round 6
// speedup vs baseline: 1.5351x; 1.5351x over previous
#include <cuda_runtime.h>
#include <math.h>

#define BATCH 16
#define DIM   48
#define HID   16
#define CH    8
#define IMG   256
#define HW    (IMG*IMG)
#define ROWS  (BATCH*HW)

typedef unsigned long long u64;

__device__ float g_x1[(size_t)ROWS * CH];   // 33.5 MB
__device__ float g_n [(size_t)ROWS * CH];   // 33.5 MB

__device__ __forceinline__ u64 pk2(float a, float b) {
    u64 r;
    asm("mov.b64 %0,{%1,%2};" : "=l"(r) : "r"(__float_as_uint(a)), "r"(__float_as_uint(b)));
    return r;
}
__device__ __forceinline__ void upk2(u64 v, float& a, float& b) {
    unsigned lo, hi;
    asm("mov.b64 {%0,%1},%2;" : "=r"(lo), "=r"(hi) : "l"(v));
    a = __uint_as_float(lo); b = __uint_as_float(hi);
}
__device__ __forceinline__ void fma2(u64& d, u64 a, u64 b) {
    asm("fma.rn.f32x2 %0,%1,%2,%0;" : "+l"(d) : "l"(a), "l"(b));
}

// A&S 7.1.26 erf-based exact-form GELU (|abs err| ~1.5e-7, validated R3-R5)
__device__ __forceinline__ float gelu_f(float v) {
    float s = fabsf(v) * 0.7071067811865476f;
    float t = __fdividef(1.0f, fmaf(0.3275911f, s, 1.0f));
    float p = fmaf(1.061405429f, t, -1.453152027f);
    p = fmaf(p, t, 1.421413741f);
    p = fmaf(p, t, -0.284496736f);
    p = fmaf(p, t, 0.254829592f);
    p *= t;
    float e = fmaf(-p, __expf(-s * s), 1.0f);
    e = copysignf(e, v);
    return 0.5f * v * (1.0f + e);
}

// ---------------------------------------------------------------------------
// K1: t = gelu(gelu(x @ W1 + b1)); x1 = t[:,:8]; n = LN(t[:,8:])
// Packed f32x2 accumulators; 85-reg ceiling for more LDG hoisting/MLP.
// ---------------------------------------------------------------------------
__global__ __launch_bounds__(256, 3) void k1_gemm_gelu_ln(
    const float* __restrict__ x, const float* __restrict__ W1,
    const float* __restrict__ b1, const float* __restrict__ gamma,
    const float* __restrict__ beta)
{
    __shared__ __align__(16) float sW1[DIM * HID];
    __shared__ u64  sb1_2[HID / 2];
    __shared__ float sg[CH], sb[CH];

    int tid = threadIdx.x;
    for (int i = tid; i < DIM * HID; i += 256) sW1[i] = W1[i];
    if (tid < HID / 2) sb1_2[tid] = pk2(b1[2 * tid], b1[2 * tid + 1]);
    if (tid < CH) { sg[tid] = gamma[tid]; sb[tid] = beta[tid]; }
    __syncthreads();

    int r = blockIdx.x * 256 + tid;
    const float4* xr = (const float4*)(x + (size_t)r * DIM);

    u64 z2[8];
    #pragma unroll
    for (int q = 0; q < 8; q++) z2[q] = sb1_2[q];

    #pragma unroll
    for (int k4 = 0; k4 < DIM / 4; k4++) {
        float4 v = xr[k4];
        float xs[4] = {v.x, v.y, v.z, v.w};
        #pragma unroll
        for (int kk = 0; kk < 4; kk++) {
            u64 xx = pk2(xs[kk], xs[kk]);
            const ulonglong2* wr = (const ulonglong2*)&sW1[(k4 * 4 + kk) * HID];
            #pragma unroll
            for (int q2 = 0; q2 < 4; q2++) {
                ulonglong2 w = wr[q2];
                fma2(z2[2 * q2],     xx, w.x);
                fma2(z2[2 * q2 + 1], xx, w.y);
            }
        }
    }

    float z[HID];
    #pragma unroll
    for (int q = 0; q < 8; q++) upk2(z2[q], z[2 * q], z[2 * q + 1]);

    #pragma unroll
    for (int j = 0; j < HID; j++) z[j] = gelu_f(gelu_f(z[j]));

    float4* o1 = (float4*)(g_x1 + (size_t)r * CH);
    o1[0] = make_float4(z[0], z[1], z[2], z[3]);
    o1[1] = make_float4(z[4], z[5], z[6], z[7]);

    float m = 0.f;
    #pragma unroll
    for (int j = 8; j < 16; j++) m += z[j];
    m *= 0.125f;
    float var = 0.f;
    #pragma unroll
    for (int j = 8; j < 16; j++) { float d = z[j] - m; var += d * d; }
    var *= 0.125f;
    float inv = rsqrtf(var + 1e-5f);

    float nn[CH];
    #pragma unroll
    for (int j = 0; j < CH; j++) nn[j] = (z[8 + j] - m) * inv * sg[j] + sb[j];

    float4* o2 = (float4*)(g_n + (size_t)r * CH);
    o2[0] = make_float4(nn[0], nn[1], nn[2], nn[3]);
    o2[1] = make_float4(nn[4], nn[5], nn[6], nn[7]);
}

// ---------------------------------------------------------------------------
// K2: R2's proven structure (32x8 tile, 1 px/thread, padded scalar sn),
// with all weight reads as LDS.128 broadcasts from transposed smem copies.
// ---------------------------------------------------------------------------
#define TX 32
#define TY 8
#define HALO_W (TX + 2)
#define HALO_H (TY + 2)
#define NPAD 9

__global__ __launch_bounds__(TX * TY, 3) void k2_conv_gate_gemm(
    const float* __restrict__ dw_w, const float* __restrict__ dw_b,
    const float* __restrict__ pw_w, const float* __restrict__ pw_b,
    const float* __restrict__ W2,   const float* __restrict__ b2,
    float* __restrict__ out)
{
    __shared__ float sn[HALO_H][HALO_W][NPAD];          // 12.3 KB
    __shared__ __align__(16) float sdwT[9 * CH];        // [tap][c]
    __shared__ __align__(16) float spwT[CH * CH];       // [cin][cout]
    __shared__ __align__(16) float sW2T[DIM * CH];      // [d][c]
    __shared__ float sdwb[CH], spwb[CH], sb2[DIM];

    int tid = threadIdx.y * TX + threadIdx.x;

    if (tid < 9 * CH) {                                 // dwT[tap][c]
        int tap = tid / CH, c = tid % CH;
        sdwT[tid] = dw_w[c * 9 + tap];
    }
    if (tid >= 96 && tid < 160) {                       // pwT[cin][cout]
        int i = tid - 96;
        int ci = i / CH, co = i % CH;
        spwT[i] = pw_w[co * CH + ci];
    }
    if (tid >= 160 && tid < 168) sdwb[tid - 160] = dw_b[tid - 160];
    if (tid >= 176 && tid < 184) spwb[tid - 176] = pw_b[tid - 176];
    if (tid >= 192 && tid < 240) sb2[tid - 192]  = b2[tid - 192];
    for (int i = tid; i < DIM * CH; i += TX * TY) {     // W2T[d][c]
        int d = i / CH, c = i % CH;
        sW2T[i] = W2[c * DIM + d];
    }

    int b   = blockIdx.z;
    int tx0 = blockIdx.x * TX;
    int ty0 = blockIdx.y * TY;
    const float* nb = g_n + (size_t)b * HW * CH;

    // Cooperative halo load (zero-pad at image borders = SAME padding)
    for (int i = tid; i < HALO_H * HALO_W; i += TX * TY) {
        int hy = i / HALO_W, hx = i % HALO_W;
        int gy = ty0 + hy - 1, gx = tx0 + hx - 1;
        float4 a = make_float4(0.f, 0.f, 0.f, 0.f);
        float4 c = make_float4(0.f, 0.f, 0.f, 0.f);
        if (gy >= 0 && gy < IMG && gx >= 0 && gx < IMG) {
            const float4* src = (const float4*)(nb + ((size_t)gy * IMG + gx) * CH);
            a = src[0]; c = src[1];
        }
        float* dst = &sn[hy][hx][0];
        dst[0] = a.x; dst[1] = a.y; dst[2] = a.z; dst[3] = a.w;
        dst[4] = c.x; dst[5] = c.y; dst[6] = c.z; dst[7] = c.w;
    }
    __syncthreads();

    const float4* sdwT4 = (const float4*)sdwT;
    const float4* spwT4 = (const float4*)spwT;
    const float4* sW2T4 = (const float4*)sW2T;

    int lx = threadIdx.x + 1, ly = threadIdx.y + 1;

    float ncen[CH];
    #pragma unroll
    for (int c = 0; c < CH; c++) ncen[c] = sn[ly][lx][c];

    // Depthwise 3x3: weights via LDS.128 broadcast, data via padded scalar LDS
    float sp[CH];
    #pragma unroll
    for (int c = 0; c < CH; c++) sp[c] = sdwb[c];
    #pragma unroll
    for (int dy = 0; dy < 3; dy++) {
        #pragma unroll
        for (int dx = 0; dx < 3; dx++) {
            int tap = dy * 3 + dx;
            float4 wA = sdwT4[tap * 2];
            float4 wB = sdwT4[tap * 2 + 1];
            const float* nv = &sn[ly + dy - 1][lx + dx - 1][0];
            sp[0] += nv[0] * wA.x; sp[1] += nv[1] * wA.y;
            sp[2] += nv[2] * wA.z; sp[3] += nv[3] * wA.w;
            sp[4] += nv[4] * wB.x; sp[5] += nv[5] * wB.y;
            sp[6] += nv[6] * wB.z; sp[7] += nv[7] * wB.w;
        }
    }

    // Pointwise 1x1 (8 -> 8): weights via LDS.128 broadcast
    float chv[CH];
    #pragma unroll
    for (int c = 0; c < CH; c++) chv[c] = spwb[c];
    #pragma unroll
    for (int i = 0; i < CH; i++) {
        float v = ncen[i];
        float4 wA = spwT4[i * 2];
        float4 wB = spwT4[i * 2 + 1];
        chv[0] += v * wA.x; chv[1] += v * wA.y;
        chv[2] += v * wA.z; chv[3] += v * wA.w;
        chv[4] += v * wB.x; chv[5] += v * wB.y;
        chv[6] += v * wB.z; chv[7] += v * wB.w;
    }

    // Gate with x1
    int p = (ty0 + threadIdx.y) * IMG + (tx0 + threadIdx.x);
    const float4* x1p = (const float4*)(g_x1 + ((size_t)b * HW + p) * CH);
    float4 xa = x1p[0], xb = x1p[1];
    float g[CH] = {xa.x, xa.y, xa.z, xa.w, xb.x, xb.y, xb.z, xb.w};
    #pragma unroll
    for (int c = 0; c < CH; c++) g[c] *= sp[c] * chv[c];

    // GEMM 8 -> 48: weights via 2x LDS.128 broadcast per d, coalesced stores
    float* ob = out + (size_t)b * DIM * HW + p;
    #pragma unroll
    for (int d = 0; d < DIM; d++) {
        float4 wA = sW2T4[d * 2], wB = sW2T4[d * 2 + 1];
        float acc = sb2[d];
        acc = fmaf(g[0], wA.x, acc); acc = fmaf(g[1], wA.y, acc);
        acc = fmaf(g[2], wA.z, acc); acc = fmaf(g[3], wA.w, acc);
        acc = fmaf(g[4], wB.x, acc); acc = fmaf(g[5], wB.y, acc);
        acc = fmaf(g[6], wB.z, acc); acc = fmaf(g[7], wB.w, acc);
        ob[(size_t)d * HW] = acc;
    }
}

extern "C" void kernel_launch(void* const* d_in, const int* in_sizes, int n_in,
                              void* d_out, int out_size)
{
    const float* x     = (const float*)d_in[0];
    const float* W1    = (const float*)d_in[1];
    const float* b1    = (const float*)d_in[2];
    const float* gamma = (const float*)d_in[3];
    const float* beta  = (const float*)d_in[4];
    const float* dw_w  = (const float*)d_in[5];
    const float* dw_b  = (const float*)d_in[6];
    const float* pw_w  = (const float*)d_in[7];
    const float* pw_b  = (const float*)d_in[8];
    const float* W2    = (const float*)d_in[9];
    const float* b2    = (const float*)d_in[10];
    float* out = (float*)d_out;

    k1_gemm_gelu_ln<<<ROWS / 256, 256>>>(x, W1, b1, gamma, beta);

    dim3 g2(IMG / TX, IMG / TY, BATCH);
    k2_conv_gate_gemm<<<g2, dim3(TX, TY)>>>(dw_w, dw_b, pw_w, pw_b, W2, b2, out);
}

// round 7
// speedup vs baseline: 1.5614x; 1.0171x over previous
#include <cuda_runtime.h>
#include <math.h>

#define BATCH 16
#define DIM   48
#define HID   16
#define CH    8
#define IMG   256
#define HW    (IMG*IMG)
#define ROWS  (BATCH*HW)

typedef unsigned long long u64;

__device__ float g_x1[(size_t)ROWS * CH];   // 33.5 MB
__device__ float g_n [(size_t)ROWS * CH];   // 33.5 MB

__device__ __forceinline__ u64 pk2(float a, float b) {
    u64 r;
    asm("mov.b64 %0,{%1,%2};" : "=l"(r) : "r"(__float_as_uint(a)), "r"(__float_as_uint(b)));
    return r;
}
__device__ __forceinline__ void upk2(u64 v, float& a, float& b) {
    unsigned lo, hi;
    asm("mov.b64 {%0,%1},%2;" : "=r"(lo), "=r"(hi) : "l"(v));
    a = __uint_as_float(lo); b = __uint_as_float(hi);
}
__device__ __forceinline__ void fma2(u64& d, u64 a, u64 b) {
    asm("fma.rn.f32x2 %0,%1,%2,%0;" : "+l"(d) : "l"(a), "l"(b));
}

// A&S 7.1.26 erf-based exact-form GELU (|abs err| ~1.5e-7, validated R3-R6)
__device__ __forceinline__ float gelu_f(float v) {
    float s = fabsf(v) * 0.7071067811865476f;
    float t = __fdividef(1.0f, fmaf(0.3275911f, s, 1.0f));
    float p = fmaf(1.061405429f, t, -1.453152027f);
    p = fmaf(p, t, 1.421413741f);
    p = fmaf(p, t, -0.284496736f);
    p = fmaf(p, t, 0.254829592f);
    p *= t;
    float e = fmaf(-p, __expf(-s * s), 1.0f);
    e = copysignf(e, v);
    return 0.5f * v * (1.0f + e);
}

// ---------------------------------------------------------------------------
// K1: lane-pair j-split. Even lane: j0-7 (x1 half) for pixels (p, p+1).
// Odd lane: j8-15 (LN half) for the same two pixels. Each lane ends up
// owning exactly the 16 contiguous floats it must store (x1 or n).
// ---------------------------------------------------------------------------
__global__ __launch_bounds__(256, 4) void k1_gemm_gelu_ln(
    const float* __restrict__ x, const float* __restrict__ W1,
    const float* __restrict__ b1, const float* __restrict__ gamma,
    const float* __restrict__ beta)
{
    __shared__ __align__(16) float sW1[DIM * HID];
    __shared__ u64  sb1_2[HID / 2];
    __shared__ float sg[CH], sb[CH];

    int tid = threadIdx.x;
    for (int i = tid; i < DIM * HID; i += 256) sW1[i] = W1[i];
    if (tid < HID / 2) sb1_2[tid] = pk2(b1[2 * tid], b1[2 * tid + 1]);
    if (tid < CH) { sg[tid] = gamma[tid]; sb[tid] = beta[tid]; }
    __syncthreads();

    int t   = blockIdx.x * 256 + tid;
    int par = tid & 1;                      // lane parity = j-half
    size_t p0 = (size_t)(t & ~1);           // pixel pair (p0, p0+1)

    const float4* xr0 = (const float4*)(x + p0 * DIM);
    const float4* xr1 = (const float4*)(x + (p0 + 1) * DIM);

    u64 zA[4], zB[4];                       // 8 j-outputs per pixel
    #pragma unroll
    for (int q = 0; q < 4; q++) { zA[q] = sb1_2[par * 4 + q]; zB[q] = zA[q]; }

    #pragma unroll
    for (int k4 = 0; k4 < DIM / 4; k4++) {
        float4 a = xr0[k4], bv = xr1[k4];
        float as[4] = {a.x, a.y, a.z, a.w};
        float bs[4] = {bv.x, bv.y, bv.z, bv.w};
        #pragma unroll
        for (int kk = 0; kk < 4; kk++) {
            u64 xa = pk2(as[kk], as[kk]);
            u64 xb = pk2(bs[kk], bs[kk]);
            const ulonglong2* wr =
                (const ulonglong2*)&sW1[(k4 * 4 + kk) * HID + par * 8];
            ulonglong2 w0 = wr[0], w1 = wr[1];
            fma2(zA[0], xa, w0.x); fma2(zA[1], xa, w0.y);
            fma2(zA[2], xa, w1.x); fma2(zA[3], xa, w1.y);
            fma2(zB[0], xb, w0.x); fma2(zB[1], xb, w0.y);
            fma2(zB[2], xb, w1.x); fma2(zB[3], xb, w1.y);
        }
    }

    float f0[CH], f1[CH];
    #pragma unroll
    for (int q = 0; q < 4; q++) {
        upk2(zA[q], f0[2 * q], f0[2 * q + 1]);
        upk2(zB[q], f1[2 * q], f1[2 * q + 1]);
    }

    #pragma unroll
    for (int j = 0; j < CH; j++) {
        f0[j] = gelu_f(gelu_f(f0[j]));
        f1[j] = gelu_f(gelu_f(f1[j]));
    }

    if (par) {
        // LayerNorm both pixels' j8-15 in place
        float m0 = 0.f, m1 = 0.f;
        #pragma unroll
        for (int j = 0; j < CH; j++) { m0 += f0[j]; m1 += f1[j]; }
        m0 *= 0.125f; m1 *= 0.125f;
        float v0 = 0.f, v1 = 0.f;
        #pragma unroll
        for (int j = 0; j < CH; j++) {
            float d0 = f0[j] - m0, d1 = f1[j] - m1;
            v0 += d0 * d0; v1 += d1 * d1;
        }
        float i0 = rsqrtf(v0 * 0.125f + 1e-5f);
        float i1 = rsqrtf(v1 * 0.125f + 1e-5f);
        #pragma unroll
        for (int j = 0; j < CH; j++) {
            f0[j] = (f0[j] - m0) * i0 * sg[j] + sb[j];
            f1[j] = (f1[j] - m1) * i1 * sg[j] + sb[j];
        }
    }

    float* dst = (par ? g_n : g_x1) + p0 * CH;   // 16 contiguous floats
    float4* o = (float4*)dst;
    o[0] = make_float4(f0[0], f0[1], f0[2], f0[3]);
    o[1] = make_float4(f0[4], f0[5], f0[6], f0[7]);
    o[2] = make_float4(f1[0], f1[1], f1[2], f1[3]);
    o[3] = make_float4(f1[4], f1[5], f1[6], f1[7]);
}

// ---------------------------------------------------------------------------
// K2: proven 32x8 tile, 1 px/thread conv+pw+gate; then lane-pair d-split
// GEMM: shfl-exchange g, even lane does d0-23, odd d24-47, both pixels,
// STG.64 pixel-pair stores.
// ---------------------------------------------------------------------------
#define TX 32
#define TY 8
#define HALO_W (TX + 2)
#define HALO_H (TY + 2)
#define NPAD 9

__global__ __launch_bounds__(TX * TY, 3) void k2_conv_gate_gemm(
    const float* __restrict__ dw_w, const float* __restrict__ dw_b,
    const float* __restrict__ pw_w, const float* __restrict__ pw_b,
    const float* __restrict__ W2,   const float* __restrict__ b2,
    float* __restrict__ out)
{
    __shared__ float sn[HALO_H][HALO_W][NPAD];          // 12.3 KB
    __shared__ __align__(16) float sdwT[9 * CH];        // [tap][c]
    __shared__ __align__(16) float spwT[CH * CH];       // [cin][cout]
    __shared__ __align__(16) float sW2T[DIM * CH];      // [d][c]
    __shared__ float sdwb[CH], spwb[CH], sb2[DIM];

    int tid = threadIdx.y * TX + threadIdx.x;

    if (tid < 9 * CH) {
        int tap = tid / CH, c = tid % CH;
        sdwT[tid] = dw_w[c * 9 + tap];
    }
    if (tid >= 96 && tid < 160) {
        int i = tid - 96;
        int ci = i / CH, co = i % CH;
        spwT[i] = pw_w[co * CH + ci];
    }
    if (tid >= 160 && tid < 168) sdwb[tid - 160] = dw_b[tid - 160];
    if (tid >= 176 && tid < 184) spwb[tid - 176] = pw_b[tid - 176];
    if (tid >= 192 && tid < 240) sb2[tid - 192]  = b2[tid - 192];
    for (int i = tid; i < DIM * CH; i += TX * TY) {
        int d = i / CH, c = i % CH;
        sW2T[i] = W2[c * DIM + d];
    }

    int b   = blockIdx.z;
    int tx0 = blockIdx.x * TX;
    int ty0 = blockIdx.y * TY;
    const float* nb = g_n + (size_t)b * HW * CH;

    for (int i = tid; i < HALO_H * HALO_W; i += TX * TY) {
        int hy = i / HALO_W, hx = i % HALO_W;
        int gy = ty0 + hy - 1, gx = tx0 + hx - 1;
        float4 a = make_float4(0.f, 0.f, 0.f, 0.f);
        float4 c = make_float4(0.f, 0.f, 0.f, 0.f);
        if (gy >= 0 && gy < IMG && gx >= 0 && gx < IMG) {
            const float4* src = (const float4*)(nb + ((size_t)gy * IMG + gx) * CH);
            a = src[0]; c = src[1];
        }
        float* dst = &sn[hy][hx][0];
        dst[0] = a.x; dst[1] = a.y; dst[2] = a.z; dst[3] = a.w;
        dst[4] = c.x; dst[5] = c.y; dst[6] = c.z; dst[7] = c.w;
    }
    __syncthreads();

    const float4* sdwT4 = (const float4*)sdwT;
    const float4* spwT4 = (const float4*)spwT;
    const float4* sW2T4 = (const float4*)sW2T;

    int lx = threadIdx.x + 1, ly = threadIdx.y + 1;

    float ncen[CH];
    #pragma unroll
    for (int c = 0; c < CH; c++) ncen[c] = sn[ly][lx][c];

    // Depthwise 3x3
    float sp[CH];
    #pragma unroll
    for (int c = 0; c < CH; c++) sp[c] = sdwb[c];
    #pragma unroll
    for (int dy = 0; dy < 3; dy++) {
        #pragma unroll
        for (int dx = 0; dx < 3; dx++) {
            int tap = dy * 3 + dx;
            float4 wA = sdwT4[tap * 2];
            float4 wB = sdwT4[tap * 2 + 1];
            const float* nv = &sn[ly + dy - 1][lx + dx - 1][0];
            sp[0] += nv[0] * wA.x; sp[1] += nv[1] * wA.y;
            sp[2] += nv[2] * wA.z; sp[3] += nv[3] * wA.w;
            sp[4] += nv[4] * wB.x; sp[5] += nv[5] * wB.y;
            sp[6] += nv[6] * wB.z; sp[7] += nv[7] * wB.w;
        }
    }

    // Pointwise 1x1
    float chv[CH];
    #pragma unroll
    for (int c = 0; c < CH; c++) chv[c] = spwb[c];
    #pragma unroll
    for (int i = 0; i < CH; i++) {
        float v = ncen[i];
        float4 wA = spwT4[i * 2];
        float4 wB = spwT4[i * 2 + 1];
        chv[0] += v * wA.x; chv[1] += v * wA.y;
        chv[2] += v * wA.z; chv[3] += v * wA.w;
        chv[4] += v * wB.x; chv[5] += v * wB.y;
        chv[6] += v * wB.z; chv[7] += v * wB.w;
    }

    // Gate with x1
    int p = (ty0 + threadIdx.y) * IMG + (tx0 + threadIdx.x);
    const float4* x1p = (const float4*)(g_x1 + ((size_t)b * HW + p) * CH);
    float4 xa = x1p[0], xb = x1p[1];
    float g[CH] = {xa.x, xa.y, xa.z, xa.w, xb.x, xb.y, xb.z, xb.w};
    #pragma unroll
    for (int c = 0; c < CH; c++) g[c] *= sp[c] * chv[c];

    // ---- lane-pair d-split GEMM: exchange g within (lane, lane^1) ----
    int par = threadIdx.x & 1;
    float ge[CH], go[CH];   // ge = even pixel's g, go = odd pixel's g
    #pragma unroll
    for (int c = 0; c < CH; c++) {
        float other = __shfl_xor_sync(0xffffffffu, g[c], 1);
        ge[c] = par ? other : g[c];
        go[c] = par ? g[c] : other;
    }

    int ppair = (ty0 + threadIdx.y) * IMG + tx0 + (threadIdx.x & ~1);
    float* ob = out + (size_t)b * DIM * HW + ppair;
    int d0 = par * (DIM / 2);

    #pragma unroll
    for (int dd = 0; dd < DIM / 2; dd++) {
        int d = d0 + dd;
        float4 wA = sW2T4[d * 2], wB = sW2T4[d * 2 + 1];
        float bb = sb2[d];
        float a0 = bb, a1 = bb;
        a0 = fmaf(ge[0], wA.x, a0); a1 = fmaf(go[0], wA.x, a1);
        a0 = fmaf(ge[1], wA.y, a0); a1 = fmaf(go[1], wA.y, a1);
        a0 = fmaf(ge[2], wA.z, a0); a1 = fmaf(go[2], wA.z, a1);
        a0 = fmaf(ge[3], wA.w, a0); a1 = fmaf(go[3], wA.w, a1);
        a0 = fmaf(ge[4], wB.x, a0); a1 = fmaf(go[4], wB.x, a1);
        a0 = fmaf(ge[5], wB.y, a0); a1 = fmaf(go[5], wB.y, a1);
        a0 = fmaf(ge[6], wB.z, a0); a1 = fmaf(go[6], wB.z, a1);
        a0 = fmaf(ge[7], wB.w, a0); a1 = fmaf(go[7], wB.w, a1);
        *(float2*)(ob + (size_t)d * HW) = make_float2(a0, a1);
    }
}

extern "C" void kernel_launch(void* const* d_in, const int* in_sizes, int n_in,
                              void* d_out, int out_size)
{
    const float* x     = (const float*)d_in[0];
    const float* W1    = (const float*)d_in[1];
    const float* b1    = (const float*)d_in[2];
    const float* gamma = (const float*)d_in[3];
    const float* beta  = (const float*)d_in[4];
    const float* dw_w  = (const float*)d_in[5];
    const float* dw_b  = (const float*)d_in[6];
    const float* pw_w  = (const float*)d_in[7];
    const float* pw_b  = (const float*)d_in[8];
    const float* W2    = (const float*)d_in[9];
    const float* b2    = (const float*)d_in[10];
    float* out = (float*)d_out;

    k1_gemm_gelu_ln<<<ROWS / 256, 256>>>(x, W1, b1, gamma, beta);

    dim3 g2(IMG / TX, IMG / TY, BATCH);
    k2_conv_gate_gemm<<<g2, dim3(TX, TY)>>>(dw_w, dw_b, pw_w, pw_b, W2, b2, out);
}